// round 15
// baseline (speedup 1.0000x reference)
#include <cuda_runtime.h>
#include <cstdint>

// Problem constants
#define BB   4096          // batch
#define HH   300           // hidden
#define TT   64            // sentence len
#define NG   1200          // 4*HH real gate columns
#define NGP  1280          // padded gate columns
#define KK   600           // 2*HH concat K
#define KKP  608           // padded K (19 * 32)
#define NCHUNK 19
#define BM   128           // CTA batch tile
#define BN   160           // CTA gate tile
#define KC   32            // K chunk
#define SAS  36            // smem row stride (floats): banks r*4 mod 32 -> conflict-free LDSM
#define A_ELEMS (BM * SAS)               // 4608 floats
#define B_ELEMS (BN * SAS)               // 5760 floats
#define STAGE_ELEMS (A_ELEMS + B_ELEMS)  // 10368 floats
#define STAGE_BYTES (STAGE_ELEMS * 4)    // 41472
#define NSTAGE 2
#define SMEM_BYTES (NSTAGE * STAGE_BYTES)  // 82944  (x2 CTAs/SM = 166 KB < 228 KB)

// -------- device scratch (no allocations allowed) --------
__device__ __align__(16) float g_Z[BB * HH];
__device__ __align__(16) float g_H0[2][BB * HH];
__device__ __align__(16) float g_H1[2][BB * HH];
__device__ __align__(16) float g_C0[BB * HH];
__device__ __align__(16) float g_C1[BB * HH];
__device__ __align__(16) float g_Wp0[NGP * KKP];
__device__ __align__(16) float g_Wp1[NGP * KKP];
__device__ __align__(16) float g_bp0[NGP];
__device__ __align__(16) float g_bp1[NGP];

__device__ __forceinline__ float tf32_round(float x) {
    float y;
    asm("cvt.rna.tf32.f32 %0, %1;" : "=f"(y) : "f"(x));
    return y;
}

__device__ __forceinline__ void mma_tf32(float c[4],
                                         uint32_t a0, uint32_t a1, uint32_t a2, uint32_t a3,
                                         uint32_t b0, uint32_t b1) {
    asm volatile(
        "mma.sync.aligned.m16n8k8.row.col.f32.tf32.tf32.f32 "
        "{%0,%1,%2,%3}, {%4,%5,%6,%7}, {%8,%9}, {%0,%1,%2,%3};"
        : "+f"(c[0]), "+f"(c[1]), "+f"(c[2]), "+f"(c[3])
        : "r"(a0), "r"(a1), "r"(a2), "r"(a3), "r"(b0), "r"(b1));
}

#define LDSM4(r, addr)                                                      \
    asm volatile("ldmatrix.sync.aligned.m8n8.x4.shared.b16 {%0,%1,%2,%3}, [%4];" \
                 : "=r"((r)[0]), "=r"((r)[1]), "=r"((r)[2]), "=r"((r)[3])   \
                 : "r"(addr))

#define LDSM2(r, addr)                                                      \
    asm volatile("ldmatrix.sync.aligned.m8n8.x2.shared.b16 {%0,%1}, [%2];"  \
                 : "=r"((r)[0]), "=r"((r)[1])                               \
                 : "r"(addr))

__device__ __forceinline__ float sigmoidf_(float x) {
    return __fdividef(1.0f, 1.0f + __expf(-x));
}
__device__ __forceinline__ float ftanh(float x) {
    float e = __expf(-2.0f * x);
    return __fdividef(1.0f - e, 1.0f + e);
}

__device__ __forceinline__ void cpa16(uint32_t dst, const float* src) {
    asm volatile("cp.async.cg.shared.global [%0], [%1], 16;\n" :: "r"(dst), "l"(src));
}
__device__ __forceinline__ void cpa16_zfill(uint32_t dst, const float* src) {
    asm volatile("cp.async.cg.shared.global [%0], [%1], 16, 0;\n" :: "r"(dst), "l"(src));
}

// -------- prep: weight permutation + tf32 pre-round (padded to NGP x KKP) --------
__global__ void prep_weights(const float* __restrict__ Wih, const float* __restrict__ Whh,
                             const float* __restrict__ bih, const float* __restrict__ bhh,
                             float* __restrict__ Wp, float* __restrict__ bp) {
    int idx = blockIdx.x * blockDim.x + threadIdx.x;
    if (idx >= NGP * KKP) return;
    int m = idx / KKP;
    int k = idx % KKP;
    float v = 0.0f;
    if (m < NG && k < KK) {
        int j = m >> 2;
        int g = m & 3;
        int srow = g * HH + j;
        v = tf32_round((k < HH) ? Wih[srow * HH + k] : Whh[srow * HH + (k - HH)]);
    }
    Wp[idx] = v;
    if (k == 0) {
        if (m < NG) {
            int j = m >> 2;
            int g = m & 3;
            bp[m] = bih[g * HH + j] + bhh[g * HH + j];
        } else bp[m] = 0.0f;
    }
}

__global__ void prep_z(const float* __restrict__ z, float* __restrict__ Z) {
    int idx = blockIdx.x * blockDim.x + threadIdx.x;
    if (idx < BB * HH) Z[idx] = tf32_round(z[idx]);
}

// -------- fused LSTM cell: 2-stage cp.async + ldmatrix + mma.sync tf32 --------
// grid (8, 32) = 256 CTAs (2/SM), 512 threads = 16 warps as 4 (row groups of 32) x
// 4 (col groups of 40); warp tile 32 x 40, acc = 40 regs.
__global__ __launch_bounds__(512, 2) void lstm_cell(
    const float* __restrict__ X,     // [BB,HH] tf32-pre-rounded
    const float* __restrict__ Hin,   // [BB,HH] tf32-pre-rounded
    float* __restrict__ Hout,        // [BB,HH] written tf32-rounded
    float* __restrict__ C,           // [BB,HH] fp32 in/out
    const float* __restrict__ Wp,    // [NGP,KKP] tf32
    const float* __restrict__ bp,    // [NGP]
    float* __restrict__ out,         // null or d_out base
    int t) {
    extern __shared__ __align__(16) float smem[];
    uint32_t smemU;
    asm("{ .reg .u64 tmp; cvta.to.shared.u64 tmp, %1; cvt.u32.u64 %0, tmp; }"
        : "=r"(smemU) : "l"(smem));

    const int tid  = threadIdx.x;
    const int warp = tid >> 5;
    const int lane = tid & 31;
    const int wr   = warp >> 2;          // 0..3 row group of 32
    const int wc   = warp & 3;           // 0..3 col group of 40
    const int rowBase = blockIdx.y * BM;
    const int mBase   = blockIdx.x * BN;

    float acc[2][5][4];
#pragma unroll
    for (int mt = 0; mt < 2; mt++)
#pragma unroll
        for (int nt = 0; nt < 5; nt++) {
            acc[mt][nt][0] = 0.f; acc[mt][nt][1] = 0.f;
            acc[mt][nt][2] = 0.f; acc[mt][nt][3] = 0.f;
        }

    // LDSM lane address bases (within stage 0)
    // A x4 (16 rows): lanes 0-7 rows0-7@k0, 8-15 rows8-15@k0, 16-23 rows0-7@k0+4, 24-31 rows8-15@k0+4
    const uint32_t aFragBase =
        smemU + (uint32_t)(((wr * 32 + (lane & 15)) * SAS + ((lane >> 4) << 2)) * 4);
    // B x4 (n-tiles 0,1): lanes 0-7 n0-7@k0, 8-15 n0-7@k0+4, 16-23 n8-15@k0, 24-31 n8-15@k0+4
    const uint32_t bFragBase =
        smemU + (uint32_t)((A_ELEMS +
                            (wc * 40 + (lane & 7) + ((lane >> 4) << 3)) * SAS +
                            (((lane >> 3) & 1) << 2)) * 4);
    // B x2 (n-tile 4): lanes 0-7 n32-39@k0, 8-15 n32-39@k0+4
    const uint32_t bFrag2Base =
        smemU + (uint32_t)((A_ELEMS +
                            (wc * 40 + 32 + (lane & 7)) * SAS +
                            (((lane >> 3) & 1) << 2)) * 4);

    // ---- async load of one K chunk (2304 granules of 16B) ----
    auto load_chunk = [&](int st, int ch) {
        const int kbase = ch * KC;
        const uint32_t a_s = smemU + st * STAGE_BYTES;
        const uint32_t b_s = a_s + A_ELEMS * 4;
#pragma unroll 1
        for (int i = tid; i < 2304; i += 512) {
            if (i < 1024) {
                int r = i >> 3, q = i & 7;
                int k = kbase + q * 4;
                uint32_t dst = a_s + (uint32_t)((r * SAS + q * 4) * 4);
                if (k < HH)          cpa16(dst, X + (size_t)(rowBase + r) * HH + k);
                else if (k < 2 * HH) cpa16(dst, Hin + (size_t)(rowBase + r) * HH + (k - HH));
                else                 cpa16_zfill(dst, X);
            } else {
                int ib = i - 1024;
                int r = ib >> 3, q = ib & 7;
                cpa16(b_s + (uint32_t)((r * SAS + q * 4) * 4),
                      Wp + (size_t)(mBase + r) * KKP + kbase + q * 4);
            }
        }
    };

    auto compute_chunk = [&](int st) {
        const uint32_t aS  = aFragBase  + st * STAGE_BYTES;
        const uint32_t bS  = bFragBase  + st * STAGE_BYTES;
        const uint32_t bS2 = bFrag2Base + st * STAGE_BYTES;
#pragma unroll
        for (int s = 0; s < KC / 8; s++) {
            const uint32_t koff = (uint32_t)(s * 32);   // 8 floats
            uint32_t a0[4], a1[4];
            LDSM4(a0, aS + koff);
            LDSM4(a1, aS + (uint32_t)(16 * SAS * 4) + koff);
            uint32_t b01[4], b23[4], b4[2];
            LDSM4(b01, bS + koff);                               // n-tiles 0,1
            LDSM4(b23, bS + (uint32_t)(16 * SAS * 4) + koff);    // n-tiles 2,3
            LDSM2(b4,  bS2 + koff);                              // n-tile 4
            mma_tf32(acc[0][0], a0[0], a0[1], a0[2], a0[3], b01[0], b01[1]);
            mma_tf32(acc[1][0], a1[0], a1[1], a1[2], a1[3], b01[0], b01[1]);
            mma_tf32(acc[0][1], a0[0], a0[1], a0[2], a0[3], b01[2], b01[3]);
            mma_tf32(acc[1][1], a1[0], a1[1], a1[2], a1[3], b01[2], b01[3]);
            mma_tf32(acc[0][2], a0[0], a0[1], a0[2], a0[3], b23[0], b23[1]);
            mma_tf32(acc[1][2], a1[0], a1[1], a1[2], a1[3], b23[0], b23[1]);
            mma_tf32(acc[0][3], a0[0], a0[1], a0[2], a0[3], b23[2], b23[3]);
            mma_tf32(acc[1][3], a1[0], a1[1], a1[2], a1[3], b23[2], b23[3]);
            mma_tf32(acc[0][4], a0[0], a0[1], a0[2], a0[3], b4[0], b4[1]);
            mma_tf32(acc[1][4], a1[0], a1[1], a1[2], a1[3], b4[0], b4[1]);
        }
    };

    // ---- 2-stage pipelined mainloop, one barrier per chunk, distance-1 prefetch ----
    load_chunk(0, 0);
    asm volatile("cp.async.commit_group;\n");
#pragma unroll 1
    for (int ch = 0; ch < NCHUNK; ch++) {
        asm volatile("cp.async.wait_group 0;\n");
        __syncthreads();   // publishes chunk ch; proves compute(ch-1) done -> stage (ch+1)%2 free
        if (ch + 1 < NCHUNK) {
            load_chunk((ch + 1) & 1, ch + 1);
            asm volatile("cp.async.commit_group;\n");
        }
        compute_chunk(ch & 1);
    }

    // ---- epilogue: bias, gate exchange via shfl, LSTM update ----
#pragma unroll
    for (int mt = 0; mt < 2; mt++) {
        const int r0 = rowBase + wr * 32 + mt * 16 + (lane >> 2);
#pragma unroll
        for (int nt = 0; nt < 5; nt++) {
            const int m = mBase + wc * 40 + nt * 8 + (lane & 3) * 2;
            const float bias0 = bp[m];
            const float bias1 = bp[m + 1];
            float v0 = acc[mt][nt][0] + bias0;
            float v1 = acc[mt][nt][1] + bias1;
            float v2 = acc[mt][nt][2] + bias0;
            float v3 = acc[mt][nt][3] + bias1;
            // pair lanes: even quad-pos holds (i,f), odd holds (g,o)
            float p0 = __shfl_xor_sync(0xffffffffu, v0, 1);
            float p1 = __shfl_xor_sync(0xffffffffu, v1, 1);
            float p2 = __shfl_xor_sync(0xffffffffu, v2, 1);
            float p3 = __shfl_xor_sync(0xffffffffu, v3, 1);
            if (!(lane & 1)) {
                const int j = m >> 2;   // m % 4 == 0 on these lanes
                if (j < HH) {
                    {
                        float i_ = sigmoidf_(v0);
                        float f_ = sigmoidf_(v1);
                        float g_ = ftanh(p0);
                        float o_ = sigmoidf_(p1);
                        float cold = C[(size_t)r0 * HH + j];
                        float cn = f_ * cold + i_ * g_;
                        float h  = o_ * ftanh(cn);
                        C[(size_t)r0 * HH + j]    = cn;
                        Hout[(size_t)r0 * HH + j] = tf32_round(h);
                        if (out) out[(size_t)r0 * (TT * HH) + t * HH + j] = h;
                    }
                    {
                        int r1 = r0 + 8;
                        float i_ = sigmoidf_(v2);
                        float f_ = sigmoidf_(v3);
                        float g_ = ftanh(p2);
                        float o_ = sigmoidf_(p3);
                        float cold = C[(size_t)r1 * HH + j];
                        float cn = f_ * cold + i_ * g_;
                        float h  = o_ * ftanh(cn);
                        C[(size_t)r1 * HH + j]    = cn;
                        Hout[(size_t)r1 * HH + j] = tf32_round(h);
                        if (out) out[(size_t)r1 * (TT * HH) + t * HH + j] = h;
                    }
                }
            }
        }
    }
}

extern "C" void kernel_launch(void* const* d_in, const int* in_sizes, int n_in,
                              void* d_out, int out_size) {
    (void)in_sizes; (void)n_in; (void)out_size;
    const float* z    = (const float*)d_in[0];
    const float* Wih0 = (const float*)d_in[1];
    const float* Whh0 = (const float*)d_in[2];
    const float* bih0 = (const float*)d_in[3];
    const float* bhh0 = (const float*)d_in[4];
    const float* Wih1 = (const float*)d_in[5];
    const float* Whh1 = (const float*)d_in[6];
    const float* bih1 = (const float*)d_in[7];
    const float* bhh1 = (const float*)d_in[8];
    float* out = (float*)d_out;

    float *Z, *H0, *H1, *C0, *C1, *Wp0, *Wp1, *bp0, *bp1;
    cudaGetSymbolAddress((void**)&Z,   g_Z);
    cudaGetSymbolAddress((void**)&H0,  g_H0);
    cudaGetSymbolAddress((void**)&H1,  g_H1);
    cudaGetSymbolAddress((void**)&C0,  g_C0);
    cudaGetSymbolAddress((void**)&C1,  g_C1);
    cudaGetSymbolAddress((void**)&Wp0, g_Wp0);
    cudaGetSymbolAddress((void**)&Wp1, g_Wp1);
    cudaGetSymbolAddress((void**)&bp0, g_bp0);
    cudaGetSymbolAddress((void**)&bp1, g_bp1);

    cudaFuncSetAttribute(lstm_cell, cudaFuncAttributeMaxDynamicSharedMemorySize, SMEM_BYTES);

    const size_t NB = (size_t)BB * HH;
    cudaMemsetAsync(H0, 0, 2 * NB * sizeof(float));
    cudaMemsetAsync(H1, 0, 2 * NB * sizeof(float));
    cudaMemsetAsync(C0, 0, NB * sizeof(float));
    cudaMemsetAsync(C1, 0, NB * sizeof(float));

    const int prepN = NGP * KKP;
    prep_weights<<<(prepN + 255) / 256, 256>>>(Wih0, Whh0, bih0, bhh0, Wp0, bp0);
    prep_weights<<<(prepN + 255) / 256, 256>>>(Wih1, Whh1, bih1, bhh1, Wp1, bp1);
    prep_z<<<((int)NB + 255) / 256, 256>>>(z, Z);

    dim3 grid(NGP / BN, BB / BM);   // (8, 32) = 256 CTAs
    for (int t = 0; t < TT; t++) {
        int ri = t & 1;
        int wi = ri ^ 1;
        const float* x0 = (t == 0) ? Z : (H1 + (size_t)ri * NB);
        lstm_cell<<<grid, 512, SMEM_BYTES>>>(x0, H0 + (size_t)ri * NB, H0 + (size_t)wi * NB,
                                             C0, Wp0, bp0, nullptr, t);
        lstm_cell<<<grid, 512, SMEM_BYTES>>>(H0 + (size_t)wi * NB, H1 + (size_t)ri * NB,
                                             H1 + (size_t)wi * NB, C1, Wp1, bp1, out, t);
    }
}

// round 17
// speedup vs baseline: 1.3619x; 1.3619x over previous
#include <cuda_runtime.h>
#include <cuda_fp16.h>
#include <cstdint>

// Problem constants
#define BB   4096          // batch
#define HH   300           // hidden
#define TT   64            // sentence len
#define NG   1200          // 4*HH real gate columns
#define NGP  1280          // padded gate columns
#define XHW  640           // XH row width (halves): x[0,300) | h[300,600) | 0-pad[600,640)
#define KKP  640           // padded K = XHW
#define KC   64            // K chunk (halves), 10 chunks
#define NCHUNK 10
#define BM   128           // CTA batch tile
#define BN   160           // CTA gate tile
#define SASH 72            // smem row stride (halves): 36 banks -> LDSM starts 4r mod 32, conflict-free
#define A_HALVES (BM * SASH)              // 9216
#define B_HALVES (BN * SASH)              // 11520
#define STAGE_BYTES ((A_HALVES + B_HALVES) * 2)  // 41472
#define NSTAGE 2
#define SMEM_BYTES (NSTAGE * STAGE_BYTES)        // 82944 (x2 CTA/SM = 166 KB)

// -------- device scratch (no allocations allowed) --------
__device__ __align__(16) __half g_XH0[2][BB * XHW];   // layer-0 input buffers (x|h|pad)
__device__ __align__(16) __half g_XH1[2][BB * XHW];   // layer-1 input buffers
__device__ __align__(16) float  g_C0[BB * HH];
__device__ __align__(16) float  g_C1[BB * HH];
__device__ __align__(16) __half g_Wp0[NGP * KKP];
__device__ __align__(16) __half g_Wp1[NGP * KKP];
__device__ __align__(16) float  g_bp0[NGP];
__device__ __align__(16) float  g_bp1[NGP];

__device__ __forceinline__ void mma_f16(float c[4],
                                        uint32_t a0, uint32_t a1, uint32_t a2, uint32_t a3,
                                        uint32_t b0, uint32_t b1) {
    asm volatile(
        "mma.sync.aligned.m16n8k16.row.col.f32.f16.f16.f32 "
        "{%0,%1,%2,%3}, {%4,%5,%6,%7}, {%8,%9}, {%0,%1,%2,%3};"
        : "+f"(c[0]), "+f"(c[1]), "+f"(c[2]), "+f"(c[3])
        : "r"(a0), "r"(a1), "r"(a2), "r"(a3), "r"(b0), "r"(b1));
}

#define LDSM4(r, addr)                                                      \
    asm volatile("ldmatrix.sync.aligned.m8n8.x4.shared.b16 {%0,%1,%2,%3}, [%4];" \
                 : "=r"((r)[0]), "=r"((r)[1]), "=r"((r)[2]), "=r"((r)[3])   \
                 : "r"(addr))

#define LDSM2(r, addr)                                                      \
    asm volatile("ldmatrix.sync.aligned.m8n8.x2.shared.b16 {%0,%1}, [%2];"  \
                 : "=r"((r)[0]), "=r"((r)[1])                               \
                 : "r"(addr))

__device__ __forceinline__ float sigmoidf_(float x) {
    return __fdividef(1.0f, 1.0f + __expf(-x));
}
__device__ __forceinline__ float ftanh(float x) {
    float e = __expf(-2.0f * x);
    return __fdividef(1.0f - e, 1.0f + e);
}

__device__ __forceinline__ void cpa16(uint32_t dst, const void* src) {
    asm volatile("cp.async.cg.shared.global [%0], [%1], 16;\n" :: "r"(dst), "l"(src));
}

// -------- prep: weight permutation + fp16 conversion (padded to NGP x KKP) --------
// Wp[m][k], m = 4*j + gate (m<1200), k<600 real; else 0.
__global__ void prep_weights(const float* __restrict__ Wih, const float* __restrict__ Whh,
                             const float* __restrict__ bih, const float* __restrict__ bhh,
                             __half* __restrict__ Wp, float* __restrict__ bp) {
    int idx = blockIdx.x * blockDim.x + threadIdx.x;
    if (idx >= NGP * KKP) return;
    int m = idx / KKP;
    int k = idx % KKP;
    float v = 0.0f;
    if (m < NG && k < 2 * HH) {
        int j = m >> 2;
        int g = m & 3;
        int srow = g * HH + j;
        v = (k < HH) ? Wih[srow * HH + k] : Whh[srow * HH + (k - HH)];
    }
    Wp[idx] = __float2half(v);
    if (k == 0) {
        if (m < NG) {
            int j = m >> 2;
            int g = m & 3;
            bp[m] = bih[g * HH + j] + bhh[g * HH + j];
        } else bp[m] = 0.0f;
    }
}

// scatter z (fp16) into the x-region of XH0[0]
__global__ void prep_z(const float* __restrict__ z, __half* __restrict__ XH) {
    int idx = blockIdx.x * blockDim.x + threadIdx.x;
    if (idx >= BB * HH) return;
    int r = idx / HH;
    int j = idx % HH;
    XH[(size_t)r * XHW + j] = __float2half(z[idx]);
}

// -------- fused LSTM cell: 2-stage cp.async + ldmatrix + mma.sync fp16 --------
// grid (8, 32) = 256 CTAs (2/SM), 512 threads = 16 warps as 4 (row groups of 32) x
// 4 (col groups of 40); warp tile 32 x 40, acc = 40 regs. K = 640 in 10 chunks of 64.
__global__ __launch_bounds__(512, 2) void lstm_cell(
    const __half* __restrict__ XH,   // [BB,XHW] packed x|h input
    __half* __restrict__ D1,         // h dest: elem (r,j) at D1[r*XHW + j]
    __half* __restrict__ D2,         // x dest for the other layer's buffer
    float* __restrict__ C,           // [BB,HH] fp32 cell state in/out
    const __half* __restrict__ Wp,   // [NGP,KKP] fp16 permuted weights
    const float* __restrict__ bp,    // [NGP]
    float* __restrict__ out,         // null or d_out base (fp32)
    int t) {
    extern __shared__ __align__(16) __half smem[];
    uint32_t smemU;
    asm("{ .reg .u64 tmp; cvta.to.shared.u64 tmp, %1; cvt.u32.u64 %0, tmp; }"
        : "=r"(smemU) : "l"(smem));

    const int tid  = threadIdx.x;
    const int warp = tid >> 5;
    const int lane = tid & 31;
    const int wr   = warp >> 2;          // 0..3 row group of 32
    const int wc   = warp & 3;           // 0..3 col group of 40
    const int rowBase = blockIdx.y * BM;
    const int mBase   = blockIdx.x * BN;

    float acc[2][5][4];
#pragma unroll
    for (int mt = 0; mt < 2; mt++)
#pragma unroll
        for (int nt = 0; nt < 5; nt++) {
            acc[mt][nt][0] = 0.f; acc[mt][nt][1] = 0.f;
            acc[mt][nt][2] = 0.f; acc[mt][nt][3] = 0.f;
        }

    // LDSM lane address bases (stage 0, byte units; halves * 2)
    // A x4: lanes 0-15 -> rows (m) 0-15 @k0..k7; lanes 16-31 -> same rows @k8..k15
    const uint32_t aFragBase =
        smemU + (uint32_t)(((wr * 32 + (lane & 15)) * SASH + ((lane >> 4) << 3)) * 2);
    // B x4: lanes 0-7 n0-7@k0, 8-15 n0-7@k8, 16-23 n8-15@k0, 24-31 n8-15@k8
    const uint32_t bFragBase =
        smemU + (uint32_t)((A_HALVES +
                            (wc * 40 + ((lane >> 4) << 3) + (lane & 7)) * SASH +
                            (((lane >> 3) & 1) << 3)) * 2);
    // B x2 (n-tile 4): lanes 0-7 n32-39@k0, 8-15 n32-39@k8
    const uint32_t bFrag2Base =
        smemU + (uint32_t)((A_HALVES +
                            (wc * 40 + 32 + (lane & 7)) * SASH +
                            (((lane >> 3) & 1) << 3)) * 2);

    // ---- async load of one K chunk (2304 granules of 16B = 8 halves), no conditionals ----
    auto load_chunk = [&](int st, int ch) {
        const int kbase = ch * KC;
        const uint32_t a_s = smemU + st * STAGE_BYTES;
        const uint32_t b_s = a_s + A_HALVES * 2;
#pragma unroll 1
        for (int i = tid; i < 2304; i += 512) {
            if (i < 1024) {
                int r = i >> 3, q = i & 7;
                cpa16(a_s + (uint32_t)((r * SASH + q * 8) * 2),
                      XH + (size_t)(rowBase + r) * XHW + kbase + q * 8);
            } else {
                int ib = i - 1024;
                int r = ib >> 3, q = ib & 7;
                cpa16(b_s + (uint32_t)((r * SASH + q * 8) * 2),
                      Wp + (size_t)(mBase + r) * KKP + kbase + q * 8);
            }
        }
    };

    auto compute_chunk = [&](int st) {
        const uint32_t aS  = aFragBase  + st * STAGE_BYTES;
        const uint32_t bS  = bFragBase  + st * STAGE_BYTES;
        const uint32_t bS2 = bFrag2Base + st * STAGE_BYTES;
#pragma unroll
        for (int s = 0; s < KC / 16; s++) {
            const uint32_t koff = (uint32_t)(s * 32);   // 16 halves = 32 bytes
            uint32_t a0[4], a1[4];
            LDSM4(a0, aS + koff);
            LDSM4(a1, aS + (uint32_t)(16 * SASH * 2) + koff);
            uint32_t b01[4], b23[4], b4[2];
            LDSM4(b01, bS + koff);                                // n-tiles 0,1
            LDSM4(b23, bS + (uint32_t)(16 * SASH * 2) + koff);    // n-tiles 2,3
            LDSM2(b4,  bS2 + koff);                               // n-tile 4
            mma_f16(acc[0][0], a0[0], a0[1], a0[2], a0[3], b01[0], b01[1]);
            mma_f16(acc[1][0], a1[0], a1[1], a1[2], a1[3], b01[0], b01[1]);
            mma_f16(acc[0][1], a0[0], a0[1], a0[2], a0[3], b01[2], b01[3]);
            mma_f16(acc[1][1], a1[0], a1[1], a1[2], a1[3], b01[2], b01[3]);
            mma_f16(acc[0][2], a0[0], a0[1], a0[2], a0[3], b23[0], b23[1]);
            mma_f16(acc[1][2], a1[0], a1[1], a1[2], a1[3], b23[0], b23[1]);
            mma_f16(acc[0][3], a0[0], a0[1], a0[2], a0[3], b23[2], b23[3]);
            mma_f16(acc[1][3], a1[0], a1[1], a1[2], a1[3], b23[2], b23[3]);
            mma_f16(acc[0][4], a0[0], a0[1], a0[2], a0[3], b4[0], b4[1]);
            mma_f16(acc[1][4], a1[0], a1[1], a1[2], a1[3], b4[0], b4[1]);
        }
    };

    // ---- 2-stage pipelined mainloop, one barrier per chunk, distance-1 prefetch ----
    load_chunk(0, 0);
    asm volatile("cp.async.commit_group;\n");
#pragma unroll 1
    for (int ch = 0; ch < NCHUNK; ch++) {
        asm volatile("cp.async.wait_group 0;\n");
        __syncthreads();   // publishes chunk ch; proves compute(ch-1) done -> other stage free
        if (ch + 1 < NCHUNK) {
            load_chunk((ch + 1) & 1, ch + 1);
            asm volatile("cp.async.commit_group;\n");
        }
        compute_chunk(ch & 1);
    }

    // ---- epilogue: bias, gate exchange via shfl, LSTM update ----
#pragma unroll
    for (int mt = 0; mt < 2; mt++) {
        const int r0 = rowBase + wr * 32 + mt * 16 + (lane >> 2);
#pragma unroll
        for (int nt = 0; nt < 5; nt++) {
            const int m = mBase + wc * 40 + nt * 8 + (lane & 3) * 2;
            const float bias0 = bp[m];
            const float bias1 = bp[m + 1];
            float v0 = acc[mt][nt][0] + bias0;
            float v1 = acc[mt][nt][1] + bias1;
            float v2 = acc[mt][nt][2] + bias0;
            float v3 = acc[mt][nt][3] + bias1;
            // pair lanes: even quad-pos holds (i,f), odd holds (g,o)
            float p0 = __shfl_xor_sync(0xffffffffu, v0, 1);
            float p1 = __shfl_xor_sync(0xffffffffu, v1, 1);
            float p2 = __shfl_xor_sync(0xffffffffu, v2, 1);
            float p3 = __shfl_xor_sync(0xffffffffu, v3, 1);
            if (!(lane & 1)) {
                const int j = m >> 2;   // m % 4 == 0 on these lanes
                if (j < HH) {
                    {
                        float i_ = sigmoidf_(v0);
                        float f_ = sigmoidf_(v1);
                        float g_ = ftanh(p0);
                        float o_ = sigmoidf_(p1);
                        float cold = C[(size_t)r0 * HH + j];
                        float cn = f_ * cold + i_ * g_;
                        float h  = o_ * ftanh(cn);
                        C[(size_t)r0 * HH + j] = cn;
                        __half hh = __float2half(h);
                        D1[(size_t)r0 * XHW + j] = hh;
                        D2[(size_t)r0 * XHW + j] = hh;
                        if (out) out[(size_t)r0 * (TT * HH) + t * HH + j] = h;
                    }
                    {
                        int r1 = r0 + 8;
                        float i_ = sigmoidf_(v2);
                        float f_ = sigmoidf_(v3);
                        float g_ = ftanh(p2);
                        float o_ = sigmoidf_(p3);
                        float cold = C[(size_t)r1 * HH + j];
                        float cn = f_ * cold + i_ * g_;
                        float h  = o_ * ftanh(cn);
                        C[(size_t)r1 * HH + j] = cn;
                        __half hh = __float2half(h);
                        D1[(size_t)r1 * XHW + j] = hh;
                        D2[(size_t)r1 * XHW + j] = hh;
                        if (out) out[(size_t)r1 * (TT * HH) + t * HH + j] = h;
                    }
                }
            }
        }
    }
}

extern "C" void kernel_launch(void* const* d_in, const int* in_sizes, int n_in,
                              void* d_out, int out_size) {
    (void)in_sizes; (void)n_in; (void)out_size;
    const float* z    = (const float*)d_in[0];
    const float* Wih0 = (const float*)d_in[1];
    const float* Whh0 = (const float*)d_in[2];
    const float* bih0 = (const float*)d_in[3];
    const float* bhh0 = (const float*)d_in[4];
    const float* Wih1 = (const float*)d_in[5];
    const float* Whh1 = (const float*)d_in[6];
    const float* bih1 = (const float*)d_in[7];
    const float* bhh1 = (const float*)d_in[8];
    float* out = (float*)d_out;

    __half *XH0, *XH1, *Wp0, *Wp1;
    float *C0, *C1, *bp0, *bp1;
    cudaGetSymbolAddress((void**)&XH0, g_XH0);
    cudaGetSymbolAddress((void**)&XH1, g_XH1);
    cudaGetSymbolAddress((void**)&C0,  g_C0);
    cudaGetSymbolAddress((void**)&C1,  g_C1);
    cudaGetSymbolAddress((void**)&Wp0, g_Wp0);
    cudaGetSymbolAddress((void**)&Wp1, g_Wp1);
    cudaGetSymbolAddress((void**)&bp0, g_bp0);
    cudaGetSymbolAddress((void**)&bp1, g_bp1);

    cudaFuncSetAttribute(lstm_cell, cudaFuncAttributeMaxDynamicSharedMemorySize, SMEM_BYTES);

    const size_t NBX = (size_t)BB * XHW;            // halves per XH buffer
    const size_t NBC = (size_t)BB * HH;
    cudaMemsetAsync(XH0, 0, 2 * NBX * sizeof(__half));
    cudaMemsetAsync(XH1, 0, 2 * NBX * sizeof(__half));
    cudaMemsetAsync(C0, 0, NBC * sizeof(float));
    cudaMemsetAsync(C1, 0, NBC * sizeof(float));

    const int prepN = NGP * KKP;
    prep_weights<<<(prepN + 255) / 256, 256>>>(Wih0, Whh0, bih0, bhh0, Wp0, bp0);
    prep_weights<<<(prepN + 255) / 256, 256>>>(Wih1, Whh1, bih1, bhh1, Wp1, bp1);
    prep_z<<<((int)NBC + 255) / 256, 256>>>(z, XH0);   // x-region of XH0 parity 0

    dim3 grid(NGP / BN, BB / BM);   // (8, 32) = 256 CTAs
    for (int t = 0; t < TT; t++) {
        int p  = t & 1;
        int wp = p ^ 1;
        // layer 0: reads XH0[p]; h -> XH0[wp].h; x for layer1 (same t) -> XH1[p].x
        lstm_cell<<<grid, 512, SMEM_BYTES>>>(
            XH0 + (size_t)p * NBX,
            XH0 + (size_t)wp * NBX + HH,
            XH1 + (size_t)p * NBX,
            C0, Wp0, bp0, nullptr, t);
        // layer 1: reads XH1[p]; h -> XH1[wp].h; feedback x for layer0 (t+1) -> XH0[wp].x
        lstm_cell<<<grid, 512, SMEM_BYTES>>>(
            XH1 + (size_t)p * NBX,
            XH1 + (size_t)wp * NBX + HH,
            XH0 + (size_t)wp * NBX,
            C1, Wp1, bp1, out, t);
    }
}